// round 7
// baseline (speedup 1.0000x reference)
#include <cuda_runtime.h>
#include <cuda_bf16.h>
#include <cuda_fp16.h>
#include <cstdint>

#define N_NODES 100000
#define N_EDGES 800000
#define F 128      // IN_FEATS == N_HIDDEN
#define C 64       // N_CLASSES

// ---------------------------------------------------------------------------
// Scratch (no cudaMalloc allowed)
// ---------------------------------------------------------------------------
__device__ __half g_xh[(size_t)N_NODES * F];           // x in fp16, 25.6 MB
__device__ __nv_bfloat16 g_hnh[(size_t)N_NODES * F];   // hn hi, 25.6 MB
__device__ __nv_bfloat16 g_hnl[(size_t)N_NODES * F];   // hn lo, 25.6 MB
__device__ __nv_bfloat16 g_w1h[F * F], g_w1l[F * F];   // W1^T as [N][K]
__device__ __nv_bfloat16 g_w2h[C * F], g_w2l[C * F];   // W2^T as [N][K]
__device__ int g_esrc[N_EDGES];
__device__ int g_deg[N_NODES];
__device__ int g_rowptr[N_NODES];
__device__ int g_cursor[N_NODES];
__device__ int g_total;

// ---------------------------------------------------------------------------
// mma.sync / ldmatrix helpers (portable PTX, OK on compute_103 virtual arch)
// ---------------------------------------------------------------------------
__device__ __forceinline__ uint32_t smem_u32(const void* p) {
    uint32_t a;
    asm("{ .reg .u64 t; cvta.to.shared.u64 t, %1; cvt.u32.u64 %0, t; }"
        : "=r"(a) : "l"(p));
    return a;
}
#define LDSM4(r0, r1, r2, r3, addr) \
    asm volatile("ldmatrix.sync.aligned.m8n8.x4.shared.b16 {%0,%1,%2,%3}, [%4];" \
                 : "=r"(r0), "=r"(r1), "=r"(r2), "=r"(r3) : "r"(addr))
#define MMA16816(c, a, b) \
    asm volatile("mma.sync.aligned.m16n8k16.row.col.f32.bf16.bf16.f32 " \
                 "{%0,%1,%2,%3}, {%4,%5,%6,%7}, {%8,%9}, {%0,%1,%2,%3};" \
                 : "+f"((c)[0]), "+f"((c)[1]), "+f"((c)[2]), "+f"((c)[3]) \
                 : "r"((a)[0]), "r"((a)[1]), "r"((a)[2]), "r"((a)[3]), \
                   "r"((b)[0]), "r"((b)[1]))

// ---------------------------------------------------------------------------
// K0: fused zero(deg,total) + weight split/transpose + x -> fp16
// ---------------------------------------------------------------------------
__global__ void k_prep(const float* __restrict__ x,
                       const float* __restrict__ W1, const float* __restrict__ W2) {
    int i = blockIdx.x * blockDim.x + threadIdx.x;
    const int NT = gridDim.x * blockDim.x;
    if (i == 0) g_total = 0;
    if (i < N_NODES) g_deg[i] = 0;
    if (i < F * F) {
        int k = i / F, n = i % F;
        float v = W1[i];                       // W1[k][n]
        __nv_bfloat16 h = __float2bfloat16(v);
        g_w1h[n * F + k] = h;
        g_w1l[n * F + k] = __float2bfloat16(v - __bfloat162float(h));
    }
    if (i < C * F) {
        int k = i / C, n = i % C;
        float v = W2[i];                       // W2[k][n]
        __nv_bfloat16 h = __float2bfloat16(v);
        g_w2h[n * F + k] = h;
        g_w2l[n * F + k] = __float2bfloat16(v - __bfloat162float(h));
    }
    // x -> fp16 (half2 granularity)
    const float2* x2 = (const float2*)x;
    __half2* xh2 = (__half2*)g_xh;
    const int n2 = N_NODES * F / 2;            // 6,400,000
    for (int e = i; e < n2; e += NT)
        xh2[e] = __float22half2_rn(x2[e]);
}

// ---------------------------------------------------------------------------
// K1: degree histogram
// ---------------------------------------------------------------------------
__global__ void k_hist(const int* __restrict__ dst) {
    int i = blockIdx.x * blockDim.x + threadIdx.x;
    if (i < N_EDGES) atomicAdd(&g_deg[dst[i]], 1);
}

// ---------------------------------------------------------------------------
// K2: UNORDERED CSR allocation. Warp-scan degrees, one atomicAdd per warp.
// Segments are contiguous (all the gather needs); placement order arbitrary.
// ---------------------------------------------------------------------------
__global__ void __launch_bounds__(256) k_alloc() {
    int v = blockIdx.x * blockDim.x + threadIdx.x;
    int lane = threadIdx.x & 31;
    int d = (v < N_NODES) ? g_deg[v] : 0;
    int incl = d;
    #pragma unroll
    for (int o = 1; o < 32; o <<= 1) {
        int t = __shfl_up_sync(0xFFFFFFFFu, incl, o);
        if (lane >= o) incl += t;
    }
    int wsum = __shfl_sync(0xFFFFFFFFu, incl, 31);
    int base = 0;
    if (lane == 31) base = atomicAdd(&g_total, wsum);
    base = __shfl_sync(0xFFFFFFFFu, base, 31);
    if (v < N_NODES) {
        int r = base + incl - d;
        g_rowptr[v] = r;
        g_cursor[v] = r;
    }
}

// ---------------------------------------------------------------------------
// K3: scatter edges into per-dst segments
// ---------------------------------------------------------------------------
__global__ void k_fill(const int* __restrict__ src, const int* __restrict__ dst) {
    int e = blockIdx.x * blockDim.x + threadIdx.x;
    if (e < N_EDGES) {
        int pos = atomicAdd(&g_cursor[dst[e]], 1);
        g_esrc[pos] = src[e];
    }
}

// ---------------------------------------------------------------------------
// K4: gather-sum per node (fp16 x reads). One warp/node, lane owns 4 feats.
// ---------------------------------------------------------------------------
__device__ __forceinline__ float4 h4_to_f4(uint2 u) {
    float2 fa = __half22float2(*(__half2*)&u.x);
    float2 fb = __half22float2(*(__half2*)&u.y);
    return make_float4(fa.x, fa.y, fb.x, fb.y);
}

__global__ void __launch_bounds__(256) k_gather() {
    int warp = (blockIdx.x * blockDim.x + threadIdx.x) >> 5;
    int lane = threadIdx.x & 31;
    if (warp >= N_NODES) return;
    const int v = warp;
    const uint2* x2 = (const uint2*)g_xh;          // 4 halfs per uint2

    float4 acc = h4_to_f4(x2[(size_t)v * 32 + lane]);   // self term
    const int start = g_rowptr[v];
    const int deg   = g_deg[v];
    const int end   = start + deg;

    int j = start;
    for (; j + 3 < end; j += 4) {                  // MLP = 4
        int s0 = __ldg(&g_esrc[j]);
        int s1 = __ldg(&g_esrc[j + 1]);
        int s2 = __ldg(&g_esrc[j + 2]);
        int s3 = __ldg(&g_esrc[j + 3]);
        float4 a = h4_to_f4(x2[(size_t)s0 * 32 + lane]);
        float4 b = h4_to_f4(x2[(size_t)s1 * 32 + lane]);
        float4 c = h4_to_f4(x2[(size_t)s2 * 32 + lane]);
        float4 d = h4_to_f4(x2[(size_t)s3 * 32 + lane]);
        acc.x += (a.x + b.x) + (c.x + d.x);
        acc.y += (a.y + b.y) + (c.y + d.y);
        acc.z += (a.z + b.z) + (c.z + d.z);
        acc.w += (a.w + b.w) + (c.w + d.w);
    }
    for (; j < end; j++) {
        int s0 = __ldg(&g_esrc[j]);
        float4 a = h4_to_f4(x2[(size_t)s0 * 32 + lane]);
        acc.x += a.x; acc.y += a.y; acc.z += a.z; acc.w += a.w;
    }

    float inv = 1.0f / (float)(deg + 1);
    acc.x *= inv; acc.y *= inv; acc.z *= inv; acc.w *= inv;

    __nv_bfloat16 h0 = __float2bfloat16(acc.x);
    __nv_bfloat16 h1 = __float2bfloat16(acc.y);
    __nv_bfloat16 h2 = __float2bfloat16(acc.z);
    __nv_bfloat16 h3 = __float2bfloat16(acc.w);
    __nv_bfloat16 l0 = __float2bfloat16(acc.x - __bfloat162float(h0));
    __nv_bfloat16 l1 = __float2bfloat16(acc.y - __bfloat162float(h1));
    __nv_bfloat16 l2 = __float2bfloat16(acc.z - __bfloat162float(h2));
    __nv_bfloat16 l3 = __float2bfloat16(acc.w - __bfloat162float(h3));

    __nv_bfloat162 ph0 = __halves2bfloat162(h0, h1);
    __nv_bfloat162 ph1 = __halves2bfloat162(h2, h3);
    __nv_bfloat162 pl0 = __halves2bfloat162(l0, l1);
    __nv_bfloat162 pl1 = __halves2bfloat162(l2, l3);
    uint2 hv, lv;
    hv.x = *(uint32_t*)&ph0; hv.y = *(uint32_t*)&ph1;
    lv.x = *(uint32_t*)&pl0; lv.y = *(uint32_t*)&pl1;
    ((uint2*)g_hnh)[(size_t)v * 32 + lane] = hv;
    ((uint2*)g_hnl)[(size_t)v * 32 + lane] = lv;
}

// ---------------------------------------------------------------------------
// K5: PERSISTENT mma.sync fused GEMM: emb = relu(hn@W1+b1); out = emb@W2+b2
// 148 CTAs loop over 128-node tiles; weights staged ONCE per CTA.
// ---------------------------------------------------------------------------
#define RS 136                              // row stride in bf16
#define RSB (RS * 2)                        // row stride in bytes (272)
#define SM_BIAS  0                          // 192 floats
#define SM_AH    1024
#define SM_AL    (SM_AH  + 128 * RSB)
#define SM_W1H   (SM_AL  + 128 * RSB)
#define SM_W1L   (SM_W1H + 128 * RSB)
#define SM_W2H   (SM_W1L + 128 * RSB)
#define SM_W2L   (SM_W2H + 64 * RSB)
#define SMEM_MM  (SM_W2L + 64 * RSB)        // 175,872 B

#define N_TILES ((N_NODES + 127) / 128)     // 782
#define GEMM_GRID 148

__global__ void __launch_bounds__(256) k_gemm_mma(
    const float* __restrict__ b1, const float* __restrict__ b2,
    float* __restrict__ out, float* __restrict__ emb)
{
    extern __shared__ char smem[];
    const uint32_t sb = smem_u32(smem);
    const int tid  = threadIdx.x;
    const int wid  = tid >> 5;
    const int lane = tid & 31;

    float* sBias = (float*)(smem + SM_BIAS);

    // --- stage bias + weights ONCE ---
    if (tid < F) sBias[tid] = b1[tid];
    else if (tid < F + C) sBias[tid] = b2[tid - F];
    {
        const uint4* w1h4 = (const uint4*)g_w1h;
        const uint4* w1l4 = (const uint4*)g_w1l;
        #pragma unroll
        for (int i = tid; i < 128 * 16; i += 256) {
            int r = i >> 4, c = i & 15;
            *(uint4*)(smem + SM_W1H + r * RSB + c * 16) = w1h4[i];
            *(uint4*)(smem + SM_W1L + r * RSB + c * 16) = w1l4[i];
        }
        const uint4* w2h4 = (const uint4*)g_w2h;
        const uint4* w2l4 = (const uint4*)g_w2l;
        #pragma unroll
        for (int i = tid; i < 64 * 16; i += 256) {
            int r = i >> 4, c = i & 15;
            *(uint4*)(smem + SM_W2H + r * RSB + c * 16) = w2h4[i];
            *(uint4*)(smem + SM_W2L + r * RSB + c * 16) = w2l4[i];
        }
    }

    // ldmatrix per-lane address components
    const int g  = lane >> 3, lr = lane & 7;
    const int a_row = lr + ((g & 1) << 3);
    const int a_kof = (g >> 1) << 3;
    const int b_row = lr + ((g >> 1) << 3);
    const int b_kof = (g & 1) << 3;
    const int wm = wid & 3;                       // M quarter
    const int wn = wid >> 2;                      // N half

    for (int tile = blockIdx.x; tile < N_TILES; tile += GEMM_GRID) {
        const int node0 = tile * 128;
        __syncthreads();   // previous iteration's smem reads complete

        // --- stage A (hn hi/lo) ---
        #pragma unroll
        for (int i = tid; i < 128 * 16; i += 256) {
            int r = i >> 4, c = i & 15;
            int node = node0 + r;
            uint4 vh = make_uint4(0, 0, 0, 0), vl = make_uint4(0, 0, 0, 0);
            if (node < N_NODES) {
                vh = ((const uint4*)g_hnh)[(size_t)node * 16 + c];
                vl = ((const uint4*)g_hnl)[(size_t)node * 16 + c];
            }
            *(uint4*)(smem + SM_AH + r * RSB + c * 16) = vh;
            *(uint4*)(smem + SM_AL + r * RSB + c * 16) = vl;
        }
        __syncthreads();

        // ================= GEMM1: [128 x 128] ==================
        float acc[2][8][4];
        #pragma unroll
        for (int m = 0; m < 2; m++)
            #pragma unroll
            for (int n = 0; n < 8; n++)
                #pragma unroll
                for (int q = 0; q < 4; q++) acc[m][n][q] = 0.f;

        #pragma unroll
        for (int ks = 0; ks < 8; ks++) {
            const int k0 = ks * 16;
            uint32_t ah[2][4], al[2][4];
            #pragma unroll
            for (int m = 0; m < 2; m++) {
                int row = wm * 32 + m * 16 + a_row;
                uint32_t off = row * RSB + (k0 + a_kof) * 2;
                LDSM4(ah[m][0], ah[m][1], ah[m][2], ah[m][3], sb + SM_AH + off);
                LDSM4(al[m][0], al[m][1], al[m][2], al[m][3], sb + SM_AL + off);
            }
            uint32_t bh[8][2], bl[8][2];
            #pragma unroll
            for (int nn = 0; nn < 4; nn++) {
                int row = wn * 64 + nn * 16 + b_row;
                uint32_t off = row * RSB + (k0 + b_kof) * 2;
                LDSM4(bh[2*nn][0], bh[2*nn][1], bh[2*nn+1][0], bh[2*nn+1][1],
                      sb + SM_W1H + off);
                LDSM4(bl[2*nn][0], bl[2*nn][1], bl[2*nn+1][0], bl[2*nn+1][1],
                      sb + SM_W1L + off);
            }
            #pragma unroll
            for (int m = 0; m < 2; m++)
                #pragma unroll
                for (int n = 0; n < 8; n++) {
                    MMA16816(acc[m][n], ah[m], bh[n]);
                    MMA16816(acc[m][n], ah[m], bl[n]);
                    MMA16816(acc[m][n], al[m], bh[n]);
                }
        }
        __syncthreads();

        // --- epilogue1: +b1, relu -> emb global; bf16 hi/lo into sAh/sAl ---
        {
            const int qr = lane >> 2;
            const int qc = (lane & 3) * 2;
            #pragma unroll
            for (int m = 0; m < 2; m++) {
                #pragma unroll
                for (int n = 0; n < 8; n++) {
                    int col = wn * 64 + n * 8 + qc;
                    float bA = sBias[col], bB = sBias[col + 1];
                    #pragma unroll
                    for (int h = 0; h < 2; h++) {
                        int row = wm * 32 + m * 16 + qr + h * 8;
                        float v0 = fmaxf(acc[m][n][h * 2 + 0] + bA, 0.f);
                        float v1 = fmaxf(acc[m][n][h * 2 + 1] + bB, 0.f);
                        int node = node0 + row;
                        if (node < N_NODES)
                            *(float2*)(emb + (size_t)node * F + col) = make_float2(v0, v1);
                        __nv_bfloat16 h0 = __float2bfloat16(v0);
                        __nv_bfloat16 h1 = __float2bfloat16(v1);
                        __nv_bfloat16 l0 = __float2bfloat16(v0 - __bfloat162float(h0));
                        __nv_bfloat16 l1 = __float2bfloat16(v1 - __bfloat162float(h1));
                        __nv_bfloat162 ph = __halves2bfloat162(h0, h1);
                        __nv_bfloat162 pl = __halves2bfloat162(l0, l1);
                        *(uint32_t*)(smem + SM_AH + row * RSB + col * 2) = *(uint32_t*)&ph;
                        *(uint32_t*)(smem + SM_AL + row * RSB + col * 2) = *(uint32_t*)&pl;
                    }
                }
            }
        }
        __syncthreads();

        // ================= GEMM2: [128 x 64] ==================
        float acc2[2][4][4];
        #pragma unroll
        for (int m = 0; m < 2; m++)
            #pragma unroll
            for (int n = 0; n < 4; n++)
                #pragma unroll
                for (int q = 0; q < 4; q++) acc2[m][n][q] = 0.f;

        #pragma unroll
        for (int ks = 0; ks < 8; ks++) {
            const int k0 = ks * 16;
            uint32_t ah[2][4], al[2][4];
            #pragma unroll
            for (int m = 0; m < 2; m++) {
                int row = wm * 32 + m * 16 + a_row;
                uint32_t off = row * RSB + (k0 + a_kof) * 2;
                LDSM4(ah[m][0], ah[m][1], ah[m][2], ah[m][3], sb + SM_AH + off);
                LDSM4(al[m][0], al[m][1], al[m][2], al[m][3], sb + SM_AL + off);
            }
            uint32_t bh[4][2], bl[4][2];
            #pragma unroll
            for (int nn = 0; nn < 2; nn++) {
                int row = wn * 32 + nn * 16 + b_row;
                uint32_t off = row * RSB + (k0 + b_kof) * 2;
                LDSM4(bh[2*nn][0], bh[2*nn][1], bh[2*nn+1][0], bh[2*nn+1][1],
                      sb + SM_W2H + off);
                LDSM4(bl[2*nn][0], bl[2*nn][1], bl[2*nn+1][0], bl[2*nn+1][1],
                      sb + SM_W2L + off);
            }
            #pragma unroll
            for (int m = 0; m < 2; m++)
                #pragma unroll
                for (int n = 0; n < 4; n++) {
                    MMA16816(acc2[m][n], ah[m], bh[n]);
                    MMA16816(acc2[m][n], ah[m], bl[n]);
                    MMA16816(acc2[m][n], al[m], bh[n]);
                }
        }

        // --- epilogue2: +b2 -> out ---
        {
            const int qr = lane >> 2;
            const int qc = (lane & 3) * 2;
            #pragma unroll
            for (int m = 0; m < 2; m++) {
                #pragma unroll
                for (int n = 0; n < 4; n++) {
                    int col = wn * 32 + n * 8 + qc;
                    float bA = sBias[F + col], bB = sBias[F + col + 1];
                    #pragma unroll
                    for (int h = 0; h < 2; h++) {
                        int row = wm * 32 + m * 16 + qr + h * 8;
                        int node = node0 + row;
                        if (node < N_NODES) {
                            float v0 = acc2[m][n][h * 2 + 0] + bA;
                            float v1 = acc2[m][n][h * 2 + 1] + bB;
                            *(float2*)(out + (size_t)node * C + col) = make_float2(v0, v1);
                        }
                    }
                }
            }
        }
    }
}

// ---------------------------------------------------------------------------
extern "C" void kernel_launch(void* const* d_in, const int* in_sizes, int n_in,
                              void* d_out, int out_size) {
    const float* x   = (const float*)d_in[0];
    const int*   src = (const int*)d_in[1];
    const int*   dst = (const int*)d_in[2];
    const float* W1  = (const float*)d_in[3];
    const float* b1  = (const float*)d_in[4];
    const float* W2  = (const float*)d_in[5];
    const float* b2  = (const float*)d_in[6];

    float* out = (float*)d_out;                       // [N_NODES, 64]
    float* emb = out + (size_t)N_NODES * C;           // [N_NODES, 128]

    // prep: zero counters + weight split + x->fp16
    k_prep<<<4096, 256>>>(x, W1, W2);
    // CSR build (unordered segments)
    k_hist<<<(N_EDGES + 255) / 256, 256>>>(dst);
    k_alloc<<<(N_NODES + 255) / 256, 256>>>();
    k_fill<<<(N_EDGES + 255) / 256, 256>>>(src, dst);
    // gather-sum + normalize + bf16 split
    k_gather<<<(N_NODES * 32 + 255) / 256, 256>>>();
    // persistent mma.sync fused GEMMs
    cudaFuncSetAttribute(k_gemm_mma, cudaFuncAttributeMaxDynamicSharedMemorySize,
                         SMEM_MM);
    k_gemm_mma<<<GEMM_GRID, 256, SMEM_MM>>>(b1, b2, out, emb);
}

// round 8
// speedup vs baseline: 1.0166x; 1.0166x over previous
#include <cuda_runtime.h>
#include <cuda_bf16.h>
#include <cstdint>

#define N_NODES 100000
#define N_EDGES 800000
#define F 128      // IN_FEATS == N_HIDDEN
#define C 64       // N_CLASSES

// ---------------------------------------------------------------------------
// Scratch (no cudaMalloc allowed)
// ---------------------------------------------------------------------------
__device__ __nv_bfloat16 g_hnh[(size_t)N_NODES * F];   // hn hi, 25.6 MB
__device__ __nv_bfloat16 g_hnl[(size_t)N_NODES * F];   // hn lo, 25.6 MB
__device__ __nv_bfloat16 g_w1h[F * F], g_w1l[F * F];   // W1^T as [N][K]
__device__ __nv_bfloat16 g_w2h[C * F], g_w2l[C * F];   // W2^T as [N][K]
__device__ int g_esrc[N_EDGES];
__device__ int g_deg[N_NODES];
__device__ int g_rowptr[N_NODES];
__device__ int g_cursor[N_NODES];
__device__ int g_total;

// ---------------------------------------------------------------------------
// mma.sync / ldmatrix helpers (portable PTX, OK on compute_103 virtual arch)
// ---------------------------------------------------------------------------
__device__ __forceinline__ uint32_t smem_u32(const void* p) {
    uint32_t a;
    asm("{ .reg .u64 t; cvta.to.shared.u64 t, %1; cvt.u32.u64 %0, t; }"
        : "=r"(a) : "l"(p));
    return a;
}
#define LDSM4(r0, r1, r2, r3, addr) \
    asm volatile("ldmatrix.sync.aligned.m8n8.x4.shared.b16 {%0,%1,%2,%3}, [%4];" \
                 : "=r"(r0), "=r"(r1), "=r"(r2), "=r"(r3) : "r"(addr))
#define MMA16816(c, a, b) \
    asm volatile("mma.sync.aligned.m16n8k16.row.col.f32.bf16.bf16.f32 " \
                 "{%0,%1,%2,%3}, {%4,%5,%6,%7}, {%8,%9}, {%0,%1,%2,%3};" \
                 : "+f"((c)[0]), "+f"((c)[1]), "+f"((c)[2]), "+f"((c)[3]) \
                 : "r"((a)[0]), "r"((a)[1]), "r"((a)[2]), "r"((a)[3]), \
                   "r"((b)[0]), "r"((b)[1]))

// ---------------------------------------------------------------------------
// K0: fused zero(deg,total) + weight split/transpose
// ---------------------------------------------------------------------------
__global__ void k_prep(const float* __restrict__ W1, const float* __restrict__ W2) {
    int i = blockIdx.x * blockDim.x + threadIdx.x;
    if (i == 0) g_total = 0;
    if (i < N_NODES) g_deg[i] = 0;
    if (i < F * F) {
        int k = i / F, n = i % F;
        float v = W1[i];                       // W1[k][n]
        __nv_bfloat16 h = __float2bfloat16(v);
        g_w1h[n * F + k] = h;
        g_w1l[n * F + k] = __float2bfloat16(v - __bfloat162float(h));
    }
    if (i < C * F) {
        int k = i / C, n = i % C;
        float v = W2[i];                       // W2[k][n]
        __nv_bfloat16 h = __float2bfloat16(v);
        g_w2h[n * F + k] = h;
        g_w2l[n * F + k] = __float2bfloat16(v - __bfloat162float(h));
    }
}

// ---------------------------------------------------------------------------
// K1: degree histogram (2 edges/thread)
// ---------------------------------------------------------------------------
__global__ void k_hist(const int* __restrict__ dst) {
    int i = (blockIdx.x * blockDim.x + threadIdx.x) * 2;
    if (i < N_EDGES)     atomicAdd(&g_deg[dst[i]], 1);
    if (i + 1 < N_EDGES) atomicAdd(&g_deg[dst[i + 1]], 1);
}

// ---------------------------------------------------------------------------
// K2: UNORDERED CSR allocation. Warp-scan degrees, one atomicAdd per warp.
// ---------------------------------------------------------------------------
__global__ void __launch_bounds__(256) k_alloc() {
    int v = blockIdx.x * blockDim.x + threadIdx.x;
    int lane = threadIdx.x & 31;
    int d = (v < N_NODES) ? g_deg[v] : 0;
    int incl = d;
    #pragma unroll
    for (int o = 1; o < 32; o <<= 1) {
        int t = __shfl_up_sync(0xFFFFFFFFu, incl, o);
        if (lane >= o) incl += t;
    }
    int wsum = __shfl_sync(0xFFFFFFFFu, incl, 31);
    int base = 0;
    if (lane == 31) base = atomicAdd(&g_total, wsum);
    base = __shfl_sync(0xFFFFFFFFu, base, 31);
    if (v < N_NODES) {
        int r = base + incl - d;
        g_rowptr[v] = r;
        g_cursor[v] = r;
    }
}

// ---------------------------------------------------------------------------
// K3: scatter edges into per-dst segments (2 edges/thread)
// ---------------------------------------------------------------------------
__global__ void k_fill(const int* __restrict__ src, const int* __restrict__ dst) {
    int i = (blockIdx.x * blockDim.x + threadIdx.x) * 2;
    if (i < N_EDGES) {
        int pos = atomicAdd(&g_cursor[dst[i]], 1);
        g_esrc[pos] = src[i];
    }
    if (i + 1 < N_EDGES) {
        int pos = atomicAdd(&g_cursor[dst[i + 1]], 1);
        g_esrc[pos] = src[i + 1];
    }
}

// ---------------------------------------------------------------------------
// K4: gather-sum per node (fp32 x). One warp/node, lane owns one float4.
// ---------------------------------------------------------------------------
__global__ void __launch_bounds__(256) k_gather(const float* __restrict__ x) {
    int warp = (blockIdx.x * blockDim.x + threadIdx.x) >> 5;
    int lane = threadIdx.x & 31;
    if (warp >= N_NODES) return;
    const int v = warp;
    const float4* x4 = (const float4*)x;

    float4 acc = x4[(size_t)v * 32 + lane];        // self term
    const int start = g_rowptr[v];
    const int deg   = g_deg[v];
    const int end   = start + deg;

    int j = start;
    for (; j + 3 < end; j += 4) {                  // MLP = 4
        int s0 = __ldg(&g_esrc[j]);
        int s1 = __ldg(&g_esrc[j + 1]);
        int s2 = __ldg(&g_esrc[j + 2]);
        int s3 = __ldg(&g_esrc[j + 3]);
        float4 a = x4[(size_t)s0 * 32 + lane];
        float4 b = x4[(size_t)s1 * 32 + lane];
        float4 c = x4[(size_t)s2 * 32 + lane];
        float4 d = x4[(size_t)s3 * 32 + lane];
        acc.x += (a.x + b.x) + (c.x + d.x);
        acc.y += (a.y + b.y) + (c.y + d.y);
        acc.z += (a.z + b.z) + (c.z + d.z);
        acc.w += (a.w + b.w) + (c.w + d.w);
    }
    for (; j < end; j++) {
        int s0 = __ldg(&g_esrc[j]);
        float4 a = x4[(size_t)s0 * 32 + lane];
        acc.x += a.x; acc.y += a.y; acc.z += a.z; acc.w += a.w;
    }

    float inv = 1.0f / (float)(deg + 1);
    acc.x *= inv; acc.y *= inv; acc.z *= inv; acc.w *= inv;

    __nv_bfloat16 h0 = __float2bfloat16(acc.x);
    __nv_bfloat16 h1 = __float2bfloat16(acc.y);
    __nv_bfloat16 h2 = __float2bfloat16(acc.z);
    __nv_bfloat16 h3 = __float2bfloat16(acc.w);
    __nv_bfloat16 l0 = __float2bfloat16(acc.x - __bfloat162float(h0));
    __nv_bfloat16 l1 = __float2bfloat16(acc.y - __bfloat162float(h1));
    __nv_bfloat16 l2 = __float2bfloat16(acc.z - __bfloat162float(h2));
    __nv_bfloat16 l3 = __float2bfloat16(acc.w - __bfloat162float(h3));

    __nv_bfloat162 ph0 = __halves2bfloat162(h0, h1);
    __nv_bfloat162 ph1 = __halves2bfloat162(h2, h3);
    __nv_bfloat162 pl0 = __halves2bfloat162(l0, l1);
    __nv_bfloat162 pl1 = __halves2bfloat162(l2, l3);
    uint2 hv, lv;
    hv.x = *(uint32_t*)&ph0; hv.y = *(uint32_t*)&ph1;
    lv.x = *(uint32_t*)&pl0; lv.y = *(uint32_t*)&pl1;
    ((uint2*)g_hnh)[(size_t)v * 32 + lane] = hv;
    ((uint2*)g_hnl)[(size_t)v * 32 + lane] = lv;
}

// ---------------------------------------------------------------------------
// K5: PERSISTENT mma.sync fused GEMM: emb = relu(hn@W1+b1); out = emb@W2+b2
// 148 CTAs loop over 128-node tiles; weights staged ONCE per CTA.
// ---------------------------------------------------------------------------
#define RS 136                              // row stride in bf16
#define RSB (RS * 2)                        // row stride in bytes (272)
#define SM_BIAS  0                          // 192 floats
#define SM_AH    1024
#define SM_AL    (SM_AH  + 128 * RSB)
#define SM_W1H   (SM_AL  + 128 * RSB)
#define SM_W1L   (SM_W1H + 128 * RSB)
#define SM_W2H   (SM_W1L + 128 * RSB)
#define SM_W2L   (SM_W2H + 64 * RSB)
#define SMEM_MM  (SM_W2L + 64 * RSB)        // 175,872 B

#define N_TILES ((N_NODES + 127) / 128)     // 782
#define GEMM_GRID 148

__global__ void __launch_bounds__(256) k_gemm_mma(
    const float* __restrict__ b1, const float* __restrict__ b2,
    float* __restrict__ out, float* __restrict__ emb)
{
    extern __shared__ char smem[];
    const uint32_t sb = smem_u32(smem);
    const int tid  = threadIdx.x;
    const int wid  = tid >> 5;
    const int lane = tid & 31;

    float* sBias = (float*)(smem + SM_BIAS);

    // --- stage bias + weights ONCE ---
    if (tid < F) sBias[tid] = b1[tid];
    else if (tid < F + C) sBias[tid] = b2[tid - F];
    {
        const uint4* w1h4 = (const uint4*)g_w1h;
        const uint4* w1l4 = (const uint4*)g_w1l;
        #pragma unroll
        for (int i = tid; i < 128 * 16; i += 256) {
            int r = i >> 4, c = i & 15;
            *(uint4*)(smem + SM_W1H + r * RSB + c * 16) = w1h4[i];
            *(uint4*)(smem + SM_W1L + r * RSB + c * 16) = w1l4[i];
        }
        const uint4* w2h4 = (const uint4*)g_w2h;
        const uint4* w2l4 = (const uint4*)g_w2l;
        #pragma unroll
        for (int i = tid; i < 64 * 16; i += 256) {
            int r = i >> 4, c = i & 15;
            *(uint4*)(smem + SM_W2H + r * RSB + c * 16) = w2h4[i];
            *(uint4*)(smem + SM_W2L + r * RSB + c * 16) = w2l4[i];
        }
    }

    // ldmatrix per-lane address components
    const int g  = lane >> 3, lr = lane & 7;
    const int a_row = lr + ((g & 1) << 3);
    const int a_kof = (g >> 1) << 3;
    const int b_row = lr + ((g >> 1) << 3);
    const int b_kof = (g & 1) << 3;
    const int wm = wid & 3;                       // M quarter
    const int wn = wid >> 2;                      // N half

    for (int tile = blockIdx.x; tile < N_TILES; tile += GEMM_GRID) {
        const int node0 = tile * 128;
        __syncthreads();   // previous iteration's smem reads complete

        // --- stage A (hn hi/lo) ---
        #pragma unroll
        for (int i = tid; i < 128 * 16; i += 256) {
            int r = i >> 4, c = i & 15;
            int node = node0 + r;
            uint4 vh = make_uint4(0, 0, 0, 0), vl = make_uint4(0, 0, 0, 0);
            if (node < N_NODES) {
                vh = ((const uint4*)g_hnh)[(size_t)node * 16 + c];
                vl = ((const uint4*)g_hnl)[(size_t)node * 16 + c];
            }
            *(uint4*)(smem + SM_AH + r * RSB + c * 16) = vh;
            *(uint4*)(smem + SM_AL + r * RSB + c * 16) = vl;
        }
        __syncthreads();

        // ================= GEMM1: [128 x 128] ==================
        float acc[2][8][4];
        #pragma unroll
        for (int m = 0; m < 2; m++)
            #pragma unroll
            for (int n = 0; n < 8; n++)
                #pragma unroll
                for (int q = 0; q < 4; q++) acc[m][n][q] = 0.f;

        #pragma unroll
        for (int ks = 0; ks < 8; ks++) {
            const int k0 = ks * 16;
            uint32_t ah[2][4], al[2][4];
            #pragma unroll
            for (int m = 0; m < 2; m++) {
                int row = wm * 32 + m * 16 + a_row;
                uint32_t off = row * RSB + (k0 + a_kof) * 2;
                LDSM4(ah[m][0], ah[m][1], ah[m][2], ah[m][3], sb + SM_AH + off);
                LDSM4(al[m][0], al[m][1], al[m][2], al[m][3], sb + SM_AL + off);
            }
            uint32_t bh[8][2], bl[8][2];
            #pragma unroll
            for (int nn = 0; nn < 4; nn++) {
                int row = wn * 64 + nn * 16 + b_row;
                uint32_t off = row * RSB + (k0 + b_kof) * 2;
                LDSM4(bh[2*nn][0], bh[2*nn][1], bh[2*nn+1][0], bh[2*nn+1][1],
                      sb + SM_W1H + off);
                LDSM4(bl[2*nn][0], bl[2*nn][1], bl[2*nn+1][0], bl[2*nn+1][1],
                      sb + SM_W1L + off);
            }
            #pragma unroll
            for (int m = 0; m < 2; m++)
                #pragma unroll
                for (int n = 0; n < 8; n++) {
                    MMA16816(acc[m][n], ah[m], bh[n]);
                    MMA16816(acc[m][n], ah[m], bl[n]);
                    MMA16816(acc[m][n], al[m], bh[n]);
                }
        }
        __syncthreads();

        // --- epilogue1: +b1, relu -> emb global; bf16 hi/lo into sAh/sAl ---
        {
            const int qr = lane >> 2;
            const int qc = (lane & 3) * 2;
            #pragma unroll
            for (int m = 0; m < 2; m++) {
                #pragma unroll
                for (int n = 0; n < 8; n++) {
                    int col = wn * 64 + n * 8 + qc;
                    float bA = sBias[col], bB = sBias[col + 1];
                    #pragma unroll
                    for (int h = 0; h < 2; h++) {
                        int row = wm * 32 + m * 16 + qr + h * 8;
                        float v0 = fmaxf(acc[m][n][h * 2 + 0] + bA, 0.f);
                        float v1 = fmaxf(acc[m][n][h * 2 + 1] + bB, 0.f);
                        int node = node0 + row;
                        if (node < N_NODES)
                            *(float2*)(emb + (size_t)node * F + col) = make_float2(v0, v1);
                        __nv_bfloat16 h0 = __float2bfloat16(v0);
                        __nv_bfloat16 h1 = __float2bfloat16(v1);
                        __nv_bfloat16 l0 = __float2bfloat16(v0 - __bfloat162float(h0));
                        __nv_bfloat16 l1 = __float2bfloat16(v1 - __bfloat162float(h1));
                        __nv_bfloat162 ph = __halves2bfloat162(h0, h1);
                        __nv_bfloat162 pl = __halves2bfloat162(l0, l1);
                        *(uint32_t*)(smem + SM_AH + row * RSB + col * 2) = *(uint32_t*)&ph;
                        *(uint32_t*)(smem + SM_AL + row * RSB + col * 2) = *(uint32_t*)&pl;
                    }
                }
            }
        }
        __syncthreads();

        // ================= GEMM2: [128 x 64] ==================
        float acc2[2][4][4];
        #pragma unroll
        for (int m = 0; m < 2; m++)
            #pragma unroll
            for (int n = 0; n < 4; n++)
                #pragma unroll
                for (int q = 0; q < 4; q++) acc2[m][n][q] = 0.f;

        #pragma unroll
        for (int ks = 0; ks < 8; ks++) {
            const int k0 = ks * 16;
            uint32_t ah[2][4], al[2][4];
            #pragma unroll
            for (int m = 0; m < 2; m++) {
                int row = wm * 32 + m * 16 + a_row;
                uint32_t off = row * RSB + (k0 + a_kof) * 2;
                LDSM4(ah[m][0], ah[m][1], ah[m][2], ah[m][3], sb + SM_AH + off);
                LDSM4(al[m][0], al[m][1], al[m][2], al[m][3], sb + SM_AL + off);
            }
            uint32_t bh[4][2], bl[4][2];
            #pragma unroll
            for (int nn = 0; nn < 2; nn++) {
                int row = wn * 32 + nn * 16 + b_row;
                uint32_t off = row * RSB + (k0 + b_kof) * 2;
                LDSM4(bh[2*nn][0], bh[2*nn][1], bh[2*nn+1][0], bh[2*nn+1][1],
                      sb + SM_W2H + off);
                LDSM4(bl[2*nn][0], bl[2*nn][1], bl[2*nn+1][0], bl[2*nn+1][1],
                      sb + SM_W2L + off);
            }
            #pragma unroll
            for (int m = 0; m < 2; m++)
                #pragma unroll
                for (int n = 0; n < 4; n++) {
                    MMA16816(acc2[m][n], ah[m], bh[n]);
                    MMA16816(acc2[m][n], ah[m], bl[n]);
                    MMA16816(acc2[m][n], al[m], bh[n]);
                }
        }

        // --- epilogue2: +b2 -> out ---
        {
            const int qr = lane >> 2;
            const int qc = (lane & 3) * 2;
            #pragma unroll
            for (int m = 0; m < 2; m++) {
                #pragma unroll
                for (int n = 0; n < 4; n++) {
                    int col = wn * 32 + n * 8 + qc;
                    float bA = sBias[F + col], bB = sBias[F + col + 1];
                    #pragma unroll
                    for (int h = 0; h < 2; h++) {
                        int row = wm * 32 + m * 16 + qr + h * 8;
                        int node = node0 + row;
                        if (node < N_NODES) {
                            float v0 = acc2[m][n][h * 2 + 0] + bA;
                            float v1 = acc2[m][n][h * 2 + 1] + bB;
                            *(float2*)(out + (size_t)node * C + col) = make_float2(v0, v1);
                        }
                    }
                }
            }
        }
    }
}

// ---------------------------------------------------------------------------
extern "C" void kernel_launch(void* const* d_in, const int* in_sizes, int n_in,
                              void* d_out, int out_size) {
    const float* x   = (const float*)d_in[0];
    const int*   src = (const int*)d_in[1];
    const int*   dst = (const int*)d_in[2];
    const float* W1  = (const float*)d_in[3];
    const float* b1  = (const float*)d_in[4];
    const float* W2  = (const float*)d_in[5];
    const float* b2  = (const float*)d_in[6];

    float* out = (float*)d_out;                       // [N_NODES, 64]
    float* emb = out + (size_t)N_NODES * C;           // [N_NODES, 128]

    // prep: zero counters + weight split
    k_prep<<<(N_NODES + 255) / 256, 256>>>(W1, W2);
    // CSR build (unordered segments)
    k_hist<<<(N_EDGES / 2 + 255) / 256, 256>>>(dst);
    k_alloc<<<(N_NODES + 255) / 256, 256>>>();
    k_fill<<<(N_EDGES / 2 + 255) / 256, 256>>>(src, dst);
    // gather-sum + normalize + bf16 split
    k_gather<<<(N_NODES * 32 + 255) / 256, 256>>>(x);
    // persistent mma.sync fused GEMMs
    cudaFuncSetAttribute(k_gemm_mma, cudaFuncAttributeMaxDynamicSharedMemorySize,
                         SMEM_MM);
    k_gemm_mma<<<GEMM_GRID, 256, SMEM_MM>>>(b1, b2, out, emb);
}